// round 13
// baseline (speedup 1.0000x reference)
#include <cuda_runtime.h>
#include <cuda_bf16.h>
#include <cstdint>
#include <math.h>

#define NN  256
#define CIN 128
#define NH  4
#define HD  32
#define NE  128

// Scratch (allocation-free rule)
__device__ __align__(16) __nv_bfloat16 g_Qb[NN*NH*NN*HD];   // bf16(scaled q)
__device__ __align__(16) __nv_bfloat16 g_Kb[NN*NH*NN*HD];   // bf16(k)
__device__ __align__(16) __nv_bfloat16 g_Vhb[NN*NH*NN*HD];  // v hi
__device__ __align__(16) __nv_bfloat16 g_Vlb[NN*NH*NN*HD];  // v lo
__device__ float g_G[NN*NN*NE];                             // sigmoid gate (fp32)
__device__ __align__(16) __nv_bfloat16 g_Ohb[NN*NN*NE];     // gated attn out hi
__device__ __align__(16) __nv_bfloat16 g_Olb[NN*NN*NE];     // gated attn out lo
__device__ __align__(16) __nv_bfloat16 g_Wh[5][128][136];   // weights hi
__device__ __align__(16) __nv_bfloat16 g_Wl[5][128][136];   // weights lo

// ---------------------------------------------------------------------------
// helpers
// ---------------------------------------------------------------------------
__device__ __forceinline__ uint32_t smem_u32(const void* p) {
    uint32_t a;
    asm("{ .reg .u64 t; cvta.to.shared.u64 t, %1; cvt.u32.u64 %0, t; }"
        : "=r"(a) : "l"(p));
    return a;
}

__device__ __forceinline__ void ldsm_x4(uint32_t* r, uint32_t addr) {
    asm volatile("ldmatrix.sync.aligned.m8n8.x4.shared.b16 {%0,%1,%2,%3}, [%4];"
        : "=r"(r[0]), "=r"(r[1]), "=r"(r[2]), "=r"(r[3]) : "r"(addr));
}

__device__ __forceinline__ void ldsm_x4_t(uint32_t* r, uint32_t addr) {
    asm volatile("ldmatrix.sync.aligned.m8n8.x4.trans.shared.b16 {%0,%1,%2,%3}, [%4];"
        : "=r"(r[0]), "=r"(r[1]), "=r"(r[2]), "=r"(r[3]) : "r"(addr));
}

__device__ __forceinline__ void mma_bf16(float* d, const uint32_t* a, const uint32_t* b) {
    asm volatile(
        "mma.sync.aligned.m16n8k16.row.col.f32.bf16.bf16.f32 "
        "{%0,%1,%2,%3}, {%4,%5,%6,%7}, {%8,%9}, {%0,%1,%2,%3};"
        : "+f"(d[0]), "+f"(d[1]), "+f"(d[2]), "+f"(d[3])
        : "r"(a[0]), "r"(a[1]), "r"(a[2]), "r"(a[3]), "r"(b[0]), "r"(b[1]));
}

__device__ __forceinline__ void cp_async16(uint32_t dst, const void* src) {
    asm volatile("cp.async.ca.shared.global [%0], [%1], 16;"
        :: "r"(dst), "l"(src));
}

// split two fp32 into packed bf16 hi-word and lo-word (RN, used off hot path)
__device__ __forceinline__ void split2(float a, float b, uint32_t& h, uint32_t& l) {
    __nv_bfloat16 ha = __float2bfloat16(a), hb = __float2bfloat16(b);
    float la = a - __bfloat162float(ha), lb = b - __bfloat162float(hb);
    __nv_bfloat16 lA = __float2bfloat16(la), lB = __float2bfloat16(lb);
    h = (uint32_t)__bfloat16_as_ushort(ha) | ((uint32_t)__bfloat16_as_ushort(hb) << 16);
    l = (uint32_t)__bfloat16_as_ushort(lA) | ((uint32_t)__bfloat16_as_ushort(lB) << 16);
}

// fast truncation split: hi = top16 bits (exact), lo = x - hi (bf16 RN).
// 1 PRMT + 2 AND + 2 FADD + 1 CVT.
__device__ __forceinline__ void fsplit2(float a, float b, uint32_t& h, uint32_t& l) {
    uint32_t ua = __float_as_uint(a), ub = __float_as_uint(b);
    uint32_t hh;
    asm("prmt.b32 %0, %1, %2, 0x7632;" : "=r"(hh) : "r"(ua), "r"(ub));
    float ra = a - __uint_as_float(ua & 0xFFFF0000u);
    float rb = b - __uint_as_float(ub & 0xFFFF0000u);
    uint32_t ll;
    asm("cvt.rn.bf16x2.f32 %0, %1, %2;" : "=r"(ll) : "f"(rb), "f"(ra));
    h = hh; l = ll;
}

__device__ __forceinline__ uint32_t pack2(float a, float b) {
    __nv_bfloat16 ha = __float2bfloat16(a), hb = __float2bfloat16(b);
    return (uint32_t)__bfloat16_as_ushort(ha) | ((uint32_t)__bfloat16_as_ushort(hb) << 16);
}

// convert 8 consecutive floats -> uint4 hi + uint4 lo
__device__ __forceinline__ void stage8(const float* s, void* dh, void* dl) {
    uint32_t h[4], l[4];
    #pragma unroll
    for (int p = 0; p < 4; p++) split2(s[2*p], s[2*p+1], h[p], l[p]);
    *(uint4*)dh = make_uint4(h[0], h[1], h[2], h[3]);
    *(uint4*)dl = make_uint4(l[0], l[1], l[2], l[3]);
}

// convert 8 consecutive floats -> uint4 hi only
__device__ __forceinline__ void stage8h(const float* s, void* dh) {
    uint32_t h[4];
    #pragma unroll
    for (int p = 0; p < 4; p++) {
        __nv_bfloat16 a = __float2bfloat16(s[2*p]), b = __float2bfloat16(s[2*p+1]);
        h[p] = (uint32_t)__bfloat16_as_ushort(a) | ((uint32_t)__bfloat16_as_ushort(b) << 16);
    }
    *(uint4*)dh = make_uint4(h[0], h[1], h[2], h[3]);
}

// ---------------------------------------------------------------------------
// Kernel 0: convert 5 weight matrices into bf16 hi/lo, padded stride 136.
// ---------------------------------------------------------------------------
__global__ __launch_bounds__(256) void convw_kernel(
    const float* __restrict__ wq, const float* __restrict__ wk,
    const float* __restrict__ wv, const float* __restrict__ wg,
    const float* __restrict__ wo)
{
    int m = blockIdx.x;
    const float* src = (m == 0) ? wq : (m == 1) ? wk : (m == 2) ? wv : (m == 3) ? wg : wo;
    for (int idx = threadIdx.x; idx < 128 * 64; idx += 256) {
        int r = idx >> 6, cp = (idx & 63) * 2;
        uint32_t h, l;
        split2(src[r * 128 + cp], src[r * 128 + cp + 1], h, l);
        *(uint32_t*)&g_Wh[m][r][cp] = h;
        *(uint32_t*)&g_Wl[m][r][cp] = l;
    }
}

// ---------------------------------------------------------------------------
// Kernel 1a: LIGHT projections (Q, K): single bf16 MMA. 4 CTAs/SM.
// ---------------------------------------------------------------------------
#define PL_XH 0
#define PL_WH 17408
#define PL_SMEM 52224

__global__ __launch_bounds__(256, 4) void proj_light_kernel(
    const float* __restrict__ qx, const float* __restrict__ kvx)
{
    extern __shared__ __align__(16) char smem[];
    const int tid = threadIdx.x, w = tid >> 5, lane = tid & 31;
    const int mi = w & 1, nh = w >> 1;
    const int mode = blockIdx.y;             // 0=Q, 1=K
    const int r0 = blockIdx.x * 64;
    const uint32_t sb = smem_u32(smem);

    {
        const char* srcH = (const char*)g_Wh[mode];
        for (int i = tid; i < 2176; i += 256)
            cp_async16(sb + PL_WH + i * 16, srcH + i * 16);
        asm volatile("cp.async.commit_group;");
    }
    {
        const float* X = (mode == 0) ? qx : kvx;
        int r = tid >> 2, c0 = (tid & 3) * 32;
        const float* src = X + (size_t)(r0 + r) * CIN + c0;
        __nv_bfloat16* dh = (__nv_bfloat16*)(smem + PL_XH) + r * 136 + c0;
        float buf[8];
        #pragma unroll
        for (int i = 0; i < 32; i += 8) {
            *(float4*)&buf[0] = *(const float4*)(src + i);
            *(float4*)&buf[4] = *(const float4*)(src + i + 4);
            stage8h(buf, dh + i);
        }
    }
    asm volatile("cp.async.wait_group 0;" ::: "memory");
    __syncthreads();

    const int lt = lane >> 3, lr = lane & 7;
    const uint32_t a_off = ((uint32_t)(mi * 32 + ((lt & 1) ? 8 : 0) + lr) * 136
                           + ((lt & 2) ? 8 : 0)) * 2;
    const uint32_t b_off = ((uint32_t)(nh * 32 + ((lt & 2) ? 8 : 0) + lr) * 136
                           + ((lt & 1) ? 8 : 0)) * 2;
    const float SCALE = 0.17677669529663687f;

    float acc[2][2][2][4];
    #pragma unroll
    for (int mf = 0; mf < 2; mf++)
        #pragma unroll
        for (int g = 0; g < 2; g++)
            #pragma unroll
            for (int j = 0; j < 2; j++)
                #pragma unroll
                for (int i = 0; i < 4; i++) acc[mf][g][j][i] = 0.f;

    #pragma unroll
    for (int k = 0; k < 8; k++) {
        uint32_t ah[2][4];
        #pragma unroll
        for (int mf = 0; mf < 2; mf++)
            ldsm_x4(ah[mf], sb + PL_XH + a_off + mf * 4352 + k * 32);
        #pragma unroll
        for (int g = 0; g < 2; g++) {
            uint32_t bh[4];
            ldsm_x4(bh, sb + PL_WH + b_off + g * 4352 + k * 32);
            #pragma unroll
            for (int mf = 0; mf < 2; mf++) {
                mma_bf16(acc[mf][g][0], ah[mf], bh);
                mma_bf16(acc[mf][g][1], ah[mf], bh+2);
            }
        }
    }

    const float sc = (mode == 0) ? SCALE : 1.f;
    __nv_bfloat16* dstb = (mode == 0) ? g_Qb : g_Kb;
    #pragma unroll
    for (int mf = 0; mf < 2; mf++) {
        const int rlo = r0 + mi * 32 + mf * 16 + (lane >> 2);
        const int rhi = rlo + 8;
        const int n_lo = rlo >> 8, q_lo = rlo & 255;
        const int n_hi = rhi >> 8, q_hi = rhi & 255;
        #pragma unroll
        for (int g = 0; g < 2; g++)
            #pragma unroll
            for (int j = 0; j < 2; j++) {
                int col = nh * 32 + g * 16 + j * 8 + 2 * (lane & 3);
                float* a = acc[mf][g][j];
                int hh = col >> 5, d = col & 31;
                size_t ilo = ((size_t)(n_lo * NH + hh) * NN + q_lo) * HD + d;
                size_t ihi = ((size_t)(n_hi * NH + hh) * NN + q_hi) * HD + d;
                *(uint32_t*)(dstb + ilo) = pack2(a[0] * sc, a[1] * sc);
                *(uint32_t*)(dstb + ihi) = pack2(a[2] * sc, a[3] * sc);
            }
    }
}

// ---------------------------------------------------------------------------
// Kernel 1b: HEAVY projections (V, gate): 3-split. 2 CTAs/SM.
// ---------------------------------------------------------------------------
#define GX_XH 0
#define GX_XL 17408
#define GX_WH 34816
#define GX_WL 69632
#define GX_SMEM 104448

__global__ __launch_bounds__(256) void proj_heavy_kernel(
    const float* __restrict__ qx, const float* __restrict__ kvx,
    const float* __restrict__ bg)
{
    extern __shared__ __align__(16) char smem[];
    const int tid = threadIdx.x, w = tid >> 5, lane = tid & 31;
    const int mi = w & 1, nh = w >> 1;
    const int mode = blockIdx.y;             // 0=V, 1=gate
    const int widx = mode + 2;
    const int r0 = blockIdx.x * 64;
    const uint32_t sb = smem_u32(smem);

    {
        const char* srcH = (const char*)g_Wh[widx];
        const char* srcL = (const char*)g_Wl[widx];
        for (int i = tid; i < 2176; i += 256) {
            cp_async16(sb + GX_WH + i * 16, srcH + i * 16);
            cp_async16(sb + GX_WL + i * 16, srcL + i * 16);
        }
        asm volatile("cp.async.commit_group;");
    }
    {
        const float* X = (mode == 0) ? kvx : qx;
        int r = tid >> 2, c0 = (tid & 3) * 32;
        const float* src = X + (size_t)(r0 + r) * CIN + c0;
        __nv_bfloat16* dh = (__nv_bfloat16*)(smem + GX_XH) + r * 136 + c0;
        __nv_bfloat16* dl = (__nv_bfloat16*)(smem + GX_XL) + r * 136 + c0;
        float buf[8];
        #pragma unroll
        for (int i = 0; i < 32; i += 8) {
            *(float4*)&buf[0] = *(const float4*)(src + i);
            *(float4*)&buf[4] = *(const float4*)(src + i + 4);
            stage8(buf, dh + i, dl + i);
        }
    }
    asm volatile("cp.async.wait_group 0;" ::: "memory");
    __syncthreads();

    const int lt = lane >> 3, lr = lane & 7;
    const uint32_t a_off = ((uint32_t)(mi * 32 + ((lt & 1) ? 8 : 0) + lr) * 136
                           + ((lt & 2) ? 8 : 0)) * 2;
    const uint32_t b_off = ((uint32_t)(nh * 32 + ((lt & 2) ? 8 : 0) + lr) * 136
                           + ((lt & 1) ? 8 : 0)) * 2;

    float acc[2][2][2][4];
    #pragma unroll
    for (int mf = 0; mf < 2; mf++)
        #pragma unroll
        for (int g = 0; g < 2; g++)
            #pragma unroll
            for (int j = 0; j < 2; j++)
                #pragma unroll
                for (int i = 0; i < 4; i++) acc[mf][g][j][i] = 0.f;

    #pragma unroll
    for (int k = 0; k < 8; k++) {
        uint32_t ah[2][4], al[2][4];
        #pragma unroll
        for (int mf = 0; mf < 2; mf++) {
            ldsm_x4(ah[mf], sb + GX_XH + a_off + mf * 4352 + k * 32);
            ldsm_x4(al[mf], sb + GX_XL + a_off + mf * 4352 + k * 32);
        }
        #pragma unroll
        for (int g = 0; g < 2; g++) {
            uint32_t bh[4], bl[4];
            uint32_t ba = sb + GX_WH + b_off + g * 4352 + k * 32;
            ldsm_x4(bh, ba);
            ldsm_x4(bl, ba + (GX_WL - GX_WH));
            #pragma unroll
            for (int mf = 0; mf < 2; mf++) {
                mma_bf16(acc[mf][g][0], ah[mf], bh); mma_bf16(acc[mf][g][1], ah[mf], bh+2);
                mma_bf16(acc[mf][g][0], ah[mf], bl); mma_bf16(acc[mf][g][1], ah[mf], bl+2);
                mma_bf16(acc[mf][g][0], al[mf], bh); mma_bf16(acc[mf][g][1], al[mf], bh+2);
            }
        }
    }

    #pragma unroll
    for (int mf = 0; mf < 2; mf++) {
        const int rlo = r0 + mi * 32 + mf * 16 + (lane >> 2);
        const int rhi = rlo + 8;
        const int n_lo = rlo >> 8, q_lo = rlo & 255;
        const int n_hi = rhi >> 8, q_hi = rhi & 255;
        #pragma unroll
        for (int g = 0; g < 2; g++)
            #pragma unroll
            for (int j = 0; j < 2; j++) {
                int col = nh * 32 + g * 16 + j * 8 + 2 * (lane & 3);
                float* a = acc[mf][g][j];
                if (mode == 0) {
                    int hh = col >> 5, d = col & 31;
                    size_t ilo = ((size_t)(n_lo * NH + hh) * NN + q_lo) * HD + d;
                    size_t ihi = ((size_t)(n_hi * NH + hh) * NN + q_hi) * HD + d;
                    uint32_t vh, vl;
                    split2(a[0], a[1], vh, vl);
                    *(uint32_t*)(g_Vhb + ilo) = vh;
                    *(uint32_t*)(g_Vlb + ilo) = vl;
                    split2(a[2], a[3], vh, vl);
                    *(uint32_t*)(g_Vhb + ihi) = vh;
                    *(uint32_t*)(g_Vlb + ihi) = vl;
                } else {
                    float b0 = bg[col], b1 = bg[col + 1];
                    *(float2*)(g_G + (size_t)rlo * NE + col) = make_float2(
                        1.f / (1.f + __expf(-(a[0] + b0))),
                        1.f / (1.f + __expf(-(a[1] + b1))));
                    *(float2*)(g_G + (size_t)rhi * NE + col) = make_float2(
                        1.f / (1.f + __expf(-(a[2] + b0))),
                        1.f / (1.f + __expf(-(a[3] + b1))));
                }
            }
    }
}

// ---------------------------------------------------------------------------
// Kernel 2: attention. grid=(NH, NN), block=256 (8 warps x 32 q).
// Q fragments loaded DIRECTLY from gmem (no smem). K/Vh/Vl staged via cp.async.
// Mainloop fused per 16-key group: QK -> bias+exp -> trunc-split -> PV.
// smem: KH, VH, VL each [256][40] = 60 KB -> 3 CTA/SM.
// ---------------------------------------------------------------------------
#define AT_KH 0
#define AT_VH 20480
#define AT_VL 40960
#define AT_SMEM 61440

__global__ __launch_bounds__(256, 3) void mma_attn_kernel(
    const float* __restrict__ mb, const float* __restrict__ tb)
{
    extern __shared__ __align__(16) char smem[];
    const int tid = threadIdx.x, w = tid >> 5, lane = tid & 31;
    const int h = blockIdx.x;
    const int n = blockIdx.y;
    const uint32_t sb = smem_u32(smem);
    const size_t base = (size_t)(n * NH + h) * NN * HD;

    // stage K, Vh, Vl (row = tid, 64B each) via cp.async
    {
        const char* sK  = (const char*)(g_Kb + base) + tid * 64;
        const char* sVh = (const char*)(g_Vhb + base) + tid * 64;
        const char* sVl = (const char*)(g_Vlb + base) + tid * 64;
        uint32_t drow = (uint32_t)tid * 80;
        #pragma unroll
        for (int i = 0; i < 4; i++) {
            cp_async16(sb + AT_KH + drow + i * 16, sK + i * 16);
            cp_async16(sb + AT_VH + drow + i * 16, sVh + i * 16);
            cp_async16(sb + AT_VL + drow + i * 16, sVl + i * 16);
        }
        asm volatile("cp.async.commit_group;");
    }

    // Q fragments straight from gmem while cp.async drains
    uint32_t aQh[2][2][4];
    {
        const __nv_bfloat16* qb = g_Qb + base + (size_t)(w * 32) * HD;
        int rl = (lane >> 2), c0 = (lane & 3) * 2;
        #pragma unroll
        for (int mf = 0; mf < 2; mf++) {
            const __nv_bfloat16* qr = qb + mf * 16 * HD;
            #pragma unroll
            for (int kd = 0; kd < 2; kd++) {
                int cc = c0 + kd * 16;
                aQh[mf][kd][0] = *(const uint32_t*)(qr + rl * HD + cc);
                aQh[mf][kd][1] = *(const uint32_t*)(qr + (rl + 8) * HD + cc);
                aQh[mf][kd][2] = *(const uint32_t*)(qr + rl * HD + cc + 8);
                aQh[mf][kd][3] = *(const uint32_t*)(qr + (rl + 8) * HD + cc + 8);
            }
        }
    }
    asm volatile("cp.async.wait_group 0;" ::: "memory");
    __syncthreads();

    const int lt = lane >> 3, lr = lane & 7;
    const uint32_t bk_off = ((((lt & 2) ? 8 : 0) + lr) * 40 + ((lt & 1) ? 8 : 0)) * 2;
    const uint32_t bv_off = (uint32_t)((lt & 1) * 8 + lr) * 80 + (uint32_t)(lt >> 1) * 16;

    const int qr00 = w * 32 + (lane >> 2);
    const float* mrow = mb + (size_t)n * NN;
    const float* tr = tb + ((size_t)h * NN + qr00) * NN;   // +8/16/24 rows via imm

    float oacc[2][4][4];
    #pragma unroll
    for (int mf = 0; mf < 2; mf++)
        #pragma unroll
        for (int f = 0; f < 4; f++)
            #pragma unroll
            for (int i = 0; i < 4; i++) oacc[mf][f][i] = 0.f;
    float s00 = 0.f, s01 = 0.f, s10 = 0.f, s11 = 0.f;

    #pragma unroll 1
    for (int gidx = 0; gidx < 16; gidx++) {              // 16-key groups
        const int k16 = gidx * 16;
        float sg[2][2][4];
        #pragma unroll
        for (int mf = 0; mf < 2; mf++)
            #pragma unroll
            for (int j = 0; j < 2; j++)
                #pragma unroll
                for (int i = 0; i < 4; i++) sg[mf][j][i] = 0.f;

        // S = Q K^T for this 16-key group
        #pragma unroll
        for (int kd = 0; kd < 2; kd++) {
            uint32_t bh[4];
            ldsm_x4(bh, sb + AT_KH + bk_off + (uint32_t)k16 * 80 + kd * 32);
            #pragma unroll
            for (int mf = 0; mf < 2; mf++) {
                mma_bf16(sg[mf][0], aQh[mf][kd], bh);
                mma_bf16(sg[mf][1], aQh[mf][kd], bh+2);
            }
        }

        // biases + exp + sums
        #pragma unroll
        for (int j = 0; j < 2; j++) {
            int kcol = k16 + j * 8 + 2 * (lane & 3);
            float2 mv  = *(const float2*)(mrow + kcol);
            float2 t00 = *(const float2*)(tr + kcol);
            float2 t01 = *(const float2*)(tr + kcol + 8 * NN);
            float2 t10 = *(const float2*)(tr + kcol + 16 * NN);
            float2 t11 = *(const float2*)(tr + kcol + 24 * NN);
            sg[0][j][0] = __expf(sg[0][j][0] + mv.x + t00.x);
            sg[0][j][1] = __expf(sg[0][j][1] + mv.y + t00.y);
            sg[0][j][2] = __expf(sg[0][j][2] + mv.x + t01.x);
            sg[0][j][3] = __expf(sg[0][j][3] + mv.y + t01.y);
            sg[1][j][0] = __expf(sg[1][j][0] + mv.x + t10.x);
            sg[1][j][1] = __expf(sg[1][j][1] + mv.y + t10.y);
            sg[1][j][2] = __expf(sg[1][j][2] + mv.x + t11.x);
            sg[1][j][3] = __expf(sg[1][j][3] + mv.y + t11.y);
            s00 += sg[0][j][0] + sg[0][j][1];
            s01 += sg[0][j][2] + sg[0][j][3];
            s10 += sg[1][j][0] + sg[1][j][1];
            s11 += sg[1][j][2] + sg[1][j][3];
        }

        // P fragments (truncation split) + PV
        uint32_t ph[2][4], pl[2][4];
        #pragma unroll
        for (int mf = 0; mf < 2; mf++) {
            fsplit2(sg[mf][0][0], sg[mf][0][1], ph[mf][0], pl[mf][0]);
            fsplit2(sg[mf][0][2], sg[mf][0][3], ph[mf][1], pl[mf][1]);
            fsplit2(sg[mf][1][0], sg[mf][1][1], ph[mf][2], pl[mf][2]);
            fsplit2(sg[mf][1][2], sg[mf][1][3], ph[mf][3], pl[mf][3]);
        }
        const uint32_t krow = (uint32_t)k16 * 80;
        #pragma unroll
        for (int ngd = 0; ngd < 2; ngd++) {
            uint32_t bh[4], bl[4];
            uint32_t ba = sb + AT_VH + krow + bv_off + ngd * 32;
            ldsm_x4_t(bh, ba);
            ldsm_x4_t(bl, ba + (AT_VL - AT_VH));
            #pragma unroll
            for (int mf = 0; mf < 2; mf++) {
                mma_bf16(oacc[mf][2*ngd],   ph[mf], bh);
                mma_bf16(oacc[mf][2*ngd+1], ph[mf], bh+2);
                mma_bf16(oacc[mf][2*ngd],   ph[mf], bl);
                mma_bf16(oacc[mf][2*ngd+1], ph[mf], bl+2);
                mma_bf16(oacc[mf][2*ngd],   pl[mf], bh);
                mma_bf16(oacc[mf][2*ngd+1], pl[mf], bh+2);
            }
        }
    }

    s00 += __shfl_xor_sync(0xffffffffu, s00, 1);
    s00 += __shfl_xor_sync(0xffffffffu, s00, 2);
    s01 += __shfl_xor_sync(0xffffffffu, s01, 1);
    s01 += __shfl_xor_sync(0xffffffffu, s01, 2);
    s10 += __shfl_xor_sync(0xffffffffu, s10, 1);
    s10 += __shfl_xor_sync(0xffffffffu, s10, 2);
    s11 += __shfl_xor_sync(0xffffffffu, s11, 1);
    s11 += __shfl_xor_sync(0xffffffffu, s11, 2);
    float inv[2][2] = {{1.f / s00, 1.f / s01}, {1.f / s10, 1.f / s11}};

    #pragma unroll
    for (int mf = 0; mf < 2; mf++) {
        const int rlo = n * NN + w * 32 + mf * 16 + (lane >> 2);
        const int rhi = rlo + 8;
        #pragma unroll
        for (int f = 0; f < 4; f++) {
            int d = f * 8 + 2 * (lane & 3);
            float2 glo = *(const float2*)(g_G + (size_t)rlo * NE + h * HD + d);
            float2 ghi = *(const float2*)(g_G + (size_t)rhi * NE + h * HD + d);
            uint32_t oh, ol;
            split2(oacc[mf][f][0] * inv[mf][0] * glo.x,
                   oacc[mf][f][1] * inv[mf][0] * glo.y, oh, ol);
            *(uint32_t*)(g_Ohb + (size_t)rlo * NE + h * HD + d) = oh;
            *(uint32_t*)(g_Olb + (size_t)rlo * NE + h * HD + d) = ol;
            split2(oacc[mf][f][2] * inv[mf][1] * ghi.x,
                   oacc[mf][f][3] * inv[mf][1] * ghi.y, oh, ol);
            *(uint32_t*)(g_Ohb + (size_t)rhi * NE + h * HD + d) = oh;
            *(uint32_t*)(g_Olb + (size_t)rhi * NE + h * HD + d) = ol;
        }
    }
}

// ---------------------------------------------------------------------------
// Kernel 3: output projection. X pre-split bf16 hi/lo via cp.async.
// ---------------------------------------------------------------------------
__global__ __launch_bounds__(256) void mma_out_kernel(
    const float* __restrict__ bo, float* __restrict__ out)
{
    extern __shared__ __align__(16) char smem[];
    const int tid = threadIdx.x, w = tid >> 5, lane = tid & 31;
    const int mi = w & 1, nh = w >> 1;
    const int r0 = blockIdx.x * 64;
    const uint32_t sb = smem_u32(smem);

    {
        const char* srcH = (const char*)g_Wh[4];
        const char* srcL = (const char*)g_Wl[4];
        for (int i = tid; i < 2176; i += 256) {
            cp_async16(sb + GX_WH + i * 16, srcH + i * 16);
            cp_async16(sb + GX_WL + i * 16, srcL + i * 16);
        }
        int r = tid >> 2, c0 = (tid & 3) * 32;
        const char* sXh = (const char*)(g_Ohb + (size_t)(r0 + r) * NE + c0);
        const char* sXl = (const char*)(g_Olb + (size_t)(r0 + r) * NE + c0);
        uint32_t drow = (uint32_t)r * 272 + (uint32_t)c0 * 2;
        #pragma unroll
        for (int i = 0; i < 4; i++) {
            cp_async16(sb + GX_XH + drow + i * 16, sXh + i * 16);
            cp_async16(sb + GX_XL + drow + i * 16, sXl + i * 16);
        }
        asm volatile("cp.async.commit_group;");
    }
    asm volatile("cp.async.wait_group 0;" ::: "memory");
    __syncthreads();

    const int lt = lane >> 3, lr = lane & 7;
    const uint32_t a_off = ((uint32_t)(mi * 32 + ((lt & 1) ? 8 : 0) + lr) * 136
                           + ((lt & 2) ? 8 : 0)) * 2;
    const uint32_t b_off = ((uint32_t)(nh * 32 + ((lt & 2) ? 8 : 0) + lr) * 136
                           + ((lt & 1) ? 8 : 0)) * 2;

    float acc[2][2][2][4];
    #pragma unroll
    for (int mf = 0; mf < 2; mf++)
        #pragma unroll
        for (int g = 0; g < 2; g++)
            #pragma unroll
            for (int j = 0; j < 2; j++)
                #pragma unroll
                for (int i = 0; i < 4; i++) acc[mf][g][j][i] = 0.f;

    #pragma unroll
    for (int k = 0; k < 8; k++) {
        uint32_t ah[2][4], al[2][4];
        #pragma unroll
        for (int mf = 0; mf < 2; mf++) {
            ldsm_x4(ah[mf], sb + GX_XH + a_off + mf * 4352 + k * 32);
            ldsm_x4(al[mf], sb + GX_XL + a_off + mf * 4352 + k * 32);
        }
        #pragma unroll
        for (int g = 0; g < 2; g++) {
            uint32_t bh[4], bl[4];
            uint32_t ba = sb + GX_WH + b_off + g * 4352 + k * 32;
            ldsm_x4(bh, ba);
            ldsm_x4(bl, ba + (GX_WL - GX_WH));
            #pragma unroll
            for (int mf = 0; mf < 2; mf++) {
                mma_bf16(acc[mf][g][0], ah[mf], bh); mma_bf16(acc[mf][g][1], ah[mf], bh+2);
                mma_bf16(acc[mf][g][0], ah[mf], bl); mma_bf16(acc[mf][g][1], ah[mf], bl+2);
                mma_bf16(acc[mf][g][0], al[mf], bh); mma_bf16(acc[mf][g][1], al[mf], bh+2);
            }
        }
    }

    #pragma unroll
    for (int mf = 0; mf < 2; mf++) {
        const int rlo = r0 + mi * 32 + mf * 16 + (lane >> 2);
        const int rhi = rlo + 8;
        #pragma unroll
        for (int g = 0; g < 2; g++)
            #pragma unroll
            for (int j = 0; j < 2; j++) {
                int cc = nh * 32 + g * 16 + j * 8 + 2 * (lane & 3);
                float b0 = bo[cc], b1 = bo[cc + 1];
                float* a = acc[mf][g][j];
                *(float2*)(out + (size_t)rlo * CIN + cc) = make_float2(a[0] + b0, a[1] + b1);
                *(float2*)(out + (size_t)rhi * CIN + cc) = make_float2(a[2] + b0, a[3] + b1);
            }
    }
}

// ---------------------------------------------------------------------------
extern "C" void kernel_launch(void* const* d_in, const int* in_sizes, int n_in,
                              void* d_out, int out_size)
{
    const float* qx  = (const float*)d_in[0];
    const float* kvx = (const float*)d_in[1];
    const float* mb  = (const float*)d_in[2];
    const float* tb  = (const float*)d_in[3];
    const float* wq  = (const float*)d_in[4];
    const float* wk  = (const float*)d_in[5];
    const float* wv  = (const float*)d_in[6];
    const float* wg  = (const float*)d_in[7];
    const float* bg  = (const float*)d_in[8];
    const float* wo  = (const float*)d_in[9];
    const float* bo  = (const float*)d_in[10];
    float* out = (float*)d_out;

    cudaFuncSetAttribute(proj_light_kernel, cudaFuncAttributeMaxDynamicSharedMemorySize, PL_SMEM);
    cudaFuncSetAttribute(proj_heavy_kernel, cudaFuncAttributeMaxDynamicSharedMemorySize, GX_SMEM);
    cudaFuncSetAttribute(mma_attn_kernel,   cudaFuncAttributeMaxDynamicSharedMemorySize, AT_SMEM);
    cudaFuncSetAttribute(mma_out_kernel,    cudaFuncAttributeMaxDynamicSharedMemorySize, GX_SMEM);

    convw_kernel<<<5, 256>>>(wq, wk, wv, wg, wo);
    proj_light_kernel<<<dim3(1024, 2), 256, PL_SMEM>>>(qx, kvx);
    proj_heavy_kernel<<<dim3(1024, 2), 256, GX_SMEM>>>(qx, kvx, bg);
    mma_attn_kernel<<<dim3(NH, NN), 256, AT_SMEM>>>(mb, tb);
    mma_out_kernel<<<1024, 256, GX_SMEM>>>(bo, out);
}

// round 14
// speedup vs baseline: 1.1918x; 1.1918x over previous
#include <cuda_runtime.h>
#include <cuda_bf16.h>
#include <cstdint>
#include <math.h>

#define NN  256
#define CIN 128
#define NH  4
#define HD  32
#define NE  128

// Scratch (allocation-free rule)
__device__ __align__(16) __nv_bfloat16 g_Qb[NN*NH*NN*HD];   // bf16(scaled q)
__device__ __align__(16) __nv_bfloat16 g_Kb[NN*NH*NN*HD];   // bf16(k)
__device__ __align__(16) __nv_bfloat16 g_Vhb[NN*NH*NN*HD];  // v hi
__device__ __align__(16) __nv_bfloat16 g_Vlb[NN*NH*NN*HD];  // v lo
__device__ float g_G[NN*NN*NE];                             // sigmoid gate (fp32)
__device__ __align__(16) __nv_bfloat16 g_Ohb[NN*NN*NE];     // gated attn out hi
__device__ __align__(16) __nv_bfloat16 g_Olb[NN*NN*NE];     // gated attn out lo
__device__ __align__(16) __nv_bfloat16 g_Wh[5][128][136];   // weights hi
__device__ __align__(16) __nv_bfloat16 g_Wl[5][128][136];   // weights lo

// ---------------------------------------------------------------------------
// helpers
// ---------------------------------------------------------------------------
__device__ __forceinline__ uint32_t smem_u32(const void* p) {
    uint32_t a;
    asm("{ .reg .u64 t; cvta.to.shared.u64 t, %1; cvt.u32.u64 %0, t; }"
        : "=r"(a) : "l"(p));
    return a;
}

__device__ __forceinline__ void ldsm_x4(uint32_t* r, uint32_t addr) {
    asm volatile("ldmatrix.sync.aligned.m8n8.x4.shared.b16 {%0,%1,%2,%3}, [%4];"
        : "=r"(r[0]), "=r"(r[1]), "=r"(r[2]), "=r"(r[3]) : "r"(addr));
}

__device__ __forceinline__ void ldsm_x4_t(uint32_t* r, uint32_t addr) {
    asm volatile("ldmatrix.sync.aligned.m8n8.x4.trans.shared.b16 {%0,%1,%2,%3}, [%4];"
        : "=r"(r[0]), "=r"(r[1]), "=r"(r[2]), "=r"(r[3]) : "r"(addr));
}

__device__ __forceinline__ void mma_bf16(float* d, const uint32_t* a, const uint32_t* b) {
    asm volatile(
        "mma.sync.aligned.m16n8k16.row.col.f32.bf16.bf16.f32 "
        "{%0,%1,%2,%3}, {%4,%5,%6,%7}, {%8,%9}, {%0,%1,%2,%3};"
        : "+f"(d[0]), "+f"(d[1]), "+f"(d[2]), "+f"(d[3])
        : "r"(a[0]), "r"(a[1]), "r"(a[2]), "r"(a[3]), "r"(b[0]), "r"(b[1]));
}

__device__ __forceinline__ void cp_async16(uint32_t dst, const void* src) {
    asm volatile("cp.async.ca.shared.global [%0], [%1], 16;"
        :: "r"(dst), "l"(src));
}

// split two fp32 into packed bf16 hi-word and lo-word (RN, off hot path)
__device__ __forceinline__ void split2(float a, float b, uint32_t& h, uint32_t& l) {
    __nv_bfloat16 ha = __float2bfloat16(a), hb = __float2bfloat16(b);
    float la = a - __bfloat162float(ha), lb = b - __bfloat162float(hb);
    __nv_bfloat16 lA = __float2bfloat16(la), lB = __float2bfloat16(lb);
    h = (uint32_t)__bfloat16_as_ushort(ha) | ((uint32_t)__bfloat16_as_ushort(hb) << 16);
    l = (uint32_t)__bfloat16_as_ushort(lA) | ((uint32_t)__bfloat16_as_ushort(lB) << 16);
}

// fast truncation split: hi = top16 bits (exact), lo = x - hi (bf16 RN).
__device__ __forceinline__ void fsplit2(float a, float b, uint32_t& h, uint32_t& l) {
    uint32_t ua = __float_as_uint(a), ub = __float_as_uint(b);
    uint32_t hh;
    asm("prmt.b32 %0, %1, %2, 0x7632;" : "=r"(hh) : "r"(ua), "r"(ub));
    float ra = a - __uint_as_float(ua & 0xFFFF0000u);
    float rb = b - __uint_as_float(ub & 0xFFFF0000u);
    uint32_t ll;
    asm("cvt.rn.bf16x2.f32 %0, %1, %2;" : "=r"(ll) : "f"(rb), "f"(ra));
    h = hh; l = ll;
}

__device__ __forceinline__ uint32_t pack2(float a, float b) {
    __nv_bfloat16 ha = __float2bfloat16(a), hb = __float2bfloat16(b);
    return (uint32_t)__bfloat16_as_ushort(ha) | ((uint32_t)__bfloat16_as_ushort(hb) << 16);
}

// convert 8 consecutive floats -> uint4 hi + uint4 lo
__device__ __forceinline__ void stage8(const float* s, void* dh, void* dl) {
    uint32_t h[4], l[4];
    #pragma unroll
    for (int p = 0; p < 4; p++) split2(s[2*p], s[2*p+1], h[p], l[p]);
    *(uint4*)dh = make_uint4(h[0], h[1], h[2], h[3]);
    *(uint4*)dl = make_uint4(l[0], l[1], l[2], l[3]);
}

// convert 8 consecutive floats -> uint4 hi only
__device__ __forceinline__ void stage8h(const float* s, void* dh) {
    uint32_t h[4];
    #pragma unroll
    for (int p = 0; p < 4; p++) {
        __nv_bfloat16 a = __float2bfloat16(s[2*p]), b = __float2bfloat16(s[2*p+1]);
        h[p] = (uint32_t)__bfloat16_as_ushort(a) | ((uint32_t)__bfloat16_as_ushort(b) << 16);
    }
    *(uint4*)dh = make_uint4(h[0], h[1], h[2], h[3]);
}

// ---------------------------------------------------------------------------
// Kernel 0: convert 5 weight matrices into bf16 hi/lo, padded stride 136.
// ---------------------------------------------------------------------------
__global__ __launch_bounds__(256) void convw_kernel(
    const float* __restrict__ wq, const float* __restrict__ wk,
    const float* __restrict__ wv, const float* __restrict__ wg,
    const float* __restrict__ wo)
{
    int m = blockIdx.x;
    const float* src = (m == 0) ? wq : (m == 1) ? wk : (m == 2) ? wv : (m == 3) ? wg : wo;
    for (int idx = threadIdx.x; idx < 128 * 64; idx += 256) {
        int r = idx >> 6, cp = (idx & 63) * 2;
        uint32_t h, l;
        split2(src[r * 128 + cp], src[r * 128 + cp + 1], h, l);
        *(uint32_t*)&g_Wh[m][r][cp] = h;
        *(uint32_t*)&g_Wl[m][r][cp] = l;
    }
}

// ---------------------------------------------------------------------------
// Kernel 1a: LIGHT projections (Q, K): single bf16 MMA. 4 CTAs/SM.
// ---------------------------------------------------------------------------
#define PL_XH 0
#define PL_WH 17408
#define PL_SMEM 52224

__global__ __launch_bounds__(256, 4) void proj_light_kernel(
    const float* __restrict__ qx, const float* __restrict__ kvx)
{
    extern __shared__ __align__(16) char smem[];
    const int tid = threadIdx.x, w = tid >> 5, lane = tid & 31;
    const int mi = w & 1, nh = w >> 1;
    const int mode = blockIdx.y;             // 0=Q, 1=K
    const int r0 = blockIdx.x * 64;
    const uint32_t sb = smem_u32(smem);

    {
        const char* srcH = (const char*)g_Wh[mode];
        for (int i = tid; i < 2176; i += 256)
            cp_async16(sb + PL_WH + i * 16, srcH + i * 16);
        asm volatile("cp.async.commit_group;");
    }
    {
        const float* X = (mode == 0) ? qx : kvx;
        int r = tid >> 2, c0 = (tid & 3) * 32;
        const float* src = X + (size_t)(r0 + r) * CIN + c0;
        __nv_bfloat16* dh = (__nv_bfloat16*)(smem + PL_XH) + r * 136 + c0;
        float buf[8];
        #pragma unroll
        for (int i = 0; i < 32; i += 8) {
            *(float4*)&buf[0] = *(const float4*)(src + i);
            *(float4*)&buf[4] = *(const float4*)(src + i + 4);
            stage8h(buf, dh + i);
        }
    }
    asm volatile("cp.async.wait_group 0;" ::: "memory");
    __syncthreads();

    const int lt = lane >> 3, lr = lane & 7;
    const uint32_t a_off = ((uint32_t)(mi * 32 + ((lt & 1) ? 8 : 0) + lr) * 136
                           + ((lt & 2) ? 8 : 0)) * 2;
    const uint32_t b_off = ((uint32_t)(nh * 32 + ((lt & 2) ? 8 : 0) + lr) * 136
                           + ((lt & 1) ? 8 : 0)) * 2;
    const float SCALE = 0.17677669529663687f;

    float acc[2][2][2][4];
    #pragma unroll
    for (int mf = 0; mf < 2; mf++)
        #pragma unroll
        for (int g = 0; g < 2; g++)
            #pragma unroll
            for (int j = 0; j < 2; j++)
                #pragma unroll
                for (int i = 0; i < 4; i++) acc[mf][g][j][i] = 0.f;

    #pragma unroll
    for (int k = 0; k < 8; k++) {
        uint32_t ah[2][4];
        #pragma unroll
        for (int mf = 0; mf < 2; mf++)
            ldsm_x4(ah[mf], sb + PL_XH + a_off + mf * 4352 + k * 32);
        #pragma unroll
        for (int g = 0; g < 2; g++) {
            uint32_t bh[4];
            ldsm_x4(bh, sb + PL_WH + b_off + g * 4352 + k * 32);
            #pragma unroll
            for (int mf = 0; mf < 2; mf++) {
                mma_bf16(acc[mf][g][0], ah[mf], bh);
                mma_bf16(acc[mf][g][1], ah[mf], bh+2);
            }
        }
    }

    const float sc = (mode == 0) ? SCALE : 1.f;
    __nv_bfloat16* dstb = (mode == 0) ? g_Qb : g_Kb;
    #pragma unroll
    for (int mf = 0; mf < 2; mf++) {
        const int rlo = r0 + mi * 32 + mf * 16 + (lane >> 2);
        const int rhi = rlo + 8;
        const int n_lo = rlo >> 8, q_lo = rlo & 255;
        const int n_hi = rhi >> 8, q_hi = rhi & 255;
        #pragma unroll
        for (int g = 0; g < 2; g++)
            #pragma unroll
            for (int j = 0; j < 2; j++) {
                int col = nh * 32 + g * 16 + j * 8 + 2 * (lane & 3);
                float* a = acc[mf][g][j];
                int hh = col >> 5, d = col & 31;
                size_t ilo = ((size_t)(n_lo * NH + hh) * NN + q_lo) * HD + d;
                size_t ihi = ((size_t)(n_hi * NH + hh) * NN + q_hi) * HD + d;
                *(uint32_t*)(dstb + ilo) = pack2(a[0] * sc, a[1] * sc);
                *(uint32_t*)(dstb + ihi) = pack2(a[2] * sc, a[3] * sc);
            }
    }
}

// ---------------------------------------------------------------------------
// Kernel 1b: HEAVY projections (V, gate): 3-split. 2 CTAs/SM.
// ---------------------------------------------------------------------------
#define GX_XH 0
#define GX_XL 17408
#define GX_WH 34816
#define GX_WL 69632
#define GX_SMEM 104448

__global__ __launch_bounds__(256) void proj_heavy_kernel(
    const float* __restrict__ qx, const float* __restrict__ kvx,
    const float* __restrict__ bg)
{
    extern __shared__ __align__(16) char smem[];
    const int tid = threadIdx.x, w = tid >> 5, lane = tid & 31;
    const int mi = w & 1, nh = w >> 1;
    const int mode = blockIdx.y;             // 0=V, 1=gate
    const int widx = mode + 2;
    const int r0 = blockIdx.x * 64;
    const uint32_t sb = smem_u32(smem);

    {
        const char* srcH = (const char*)g_Wh[widx];
        const char* srcL = (const char*)g_Wl[widx];
        for (int i = tid; i < 2176; i += 256) {
            cp_async16(sb + GX_WH + i * 16, srcH + i * 16);
            cp_async16(sb + GX_WL + i * 16, srcL + i * 16);
        }
        asm volatile("cp.async.commit_group;");
    }
    {
        const float* X = (mode == 0) ? kvx : qx;
        int r = tid >> 2, c0 = (tid & 3) * 32;
        const float* src = X + (size_t)(r0 + r) * CIN + c0;
        __nv_bfloat16* dh = (__nv_bfloat16*)(smem + GX_XH) + r * 136 + c0;
        __nv_bfloat16* dl = (__nv_bfloat16*)(smem + GX_XL) + r * 136 + c0;
        float buf[8];
        #pragma unroll
        for (int i = 0; i < 32; i += 8) {
            *(float4*)&buf[0] = *(const float4*)(src + i);
            *(float4*)&buf[4] = *(const float4*)(src + i + 4);
            stage8(buf, dh + i, dl + i);
        }
    }
    asm volatile("cp.async.wait_group 0;" ::: "memory");
    __syncthreads();

    const int lt = lane >> 3, lr = lane & 7;
    const uint32_t a_off = ((uint32_t)(mi * 32 + ((lt & 1) ? 8 : 0) + lr) * 136
                           + ((lt & 2) ? 8 : 0)) * 2;
    const uint32_t b_off = ((uint32_t)(nh * 32 + ((lt & 2) ? 8 : 0) + lr) * 136
                           + ((lt & 1) ? 8 : 0)) * 2;

    float acc[2][2][2][4];
    #pragma unroll
    for (int mf = 0; mf < 2; mf++)
        #pragma unroll
        for (int g = 0; g < 2; g++)
            #pragma unroll
            for (int j = 0; j < 2; j++)
                #pragma unroll
                for (int i = 0; i < 4; i++) acc[mf][g][j][i] = 0.f;

    #pragma unroll
    for (int k = 0; k < 8; k++) {
        uint32_t ah[2][4], al[2][4];
        #pragma unroll
        for (int mf = 0; mf < 2; mf++) {
            ldsm_x4(ah[mf], sb + GX_XH + a_off + mf * 4352 + k * 32);
            ldsm_x4(al[mf], sb + GX_XL + a_off + mf * 4352 + k * 32);
        }
        #pragma unroll
        for (int g = 0; g < 2; g++) {
            uint32_t bh[4], bl[4];
            uint32_t ba = sb + GX_WH + b_off + g * 4352 + k * 32;
            ldsm_x4(bh, ba);
            ldsm_x4(bl, ba + (GX_WL - GX_WH));
            #pragma unroll
            for (int mf = 0; mf < 2; mf++) {
                mma_bf16(acc[mf][g][0], ah[mf], bh); mma_bf16(acc[mf][g][1], ah[mf], bh+2);
                mma_bf16(acc[mf][g][0], ah[mf], bl); mma_bf16(acc[mf][g][1], ah[mf], bl+2);
                mma_bf16(acc[mf][g][0], al[mf], bh); mma_bf16(acc[mf][g][1], al[mf], bh+2);
            }
        }
    }

    #pragma unroll
    for (int mf = 0; mf < 2; mf++) {
        const int rlo = r0 + mi * 32 + mf * 16 + (lane >> 2);
        const int rhi = rlo + 8;
        const int n_lo = rlo >> 8, q_lo = rlo & 255;
        const int n_hi = rhi >> 8, q_hi = rhi & 255;
        #pragma unroll
        for (int g = 0; g < 2; g++)
            #pragma unroll
            for (int j = 0; j < 2; j++) {
                int col = nh * 32 + g * 16 + j * 8 + 2 * (lane & 3);
                float* a = acc[mf][g][j];
                if (mode == 0) {
                    int hh = col >> 5, d = col & 31;
                    size_t ilo = ((size_t)(n_lo * NH + hh) * NN + q_lo) * HD + d;
                    size_t ihi = ((size_t)(n_hi * NH + hh) * NN + q_hi) * HD + d;
                    uint32_t vh, vl;
                    split2(a[0], a[1], vh, vl);
                    *(uint32_t*)(g_Vhb + ilo) = vh;
                    *(uint32_t*)(g_Vlb + ilo) = vl;
                    split2(a[2], a[3], vh, vl);
                    *(uint32_t*)(g_Vhb + ihi) = vh;
                    *(uint32_t*)(g_Vlb + ihi) = vl;
                } else {
                    float b0 = bg[col], b1 = bg[col + 1];
                    *(float2*)(g_G + (size_t)rlo * NE + col) = make_float2(
                        1.f / (1.f + __expf(-(a[0] + b0))),
                        1.f / (1.f + __expf(-(a[1] + b1))));
                    *(float2*)(g_G + (size_t)rhi * NE + col) = make_float2(
                        1.f / (1.f + __expf(-(a[2] + b0))),
                        1.f / (1.f + __expf(-(a[3] + b1))));
                }
            }
    }
}

// ---------------------------------------------------------------------------
// Kernel 2: attention. grid=(NH, NN), block=256 (8 warps x 32 q).
// R12 phase-separated 32-key-chunk mainloop (ILP) + Q direct from gmem +
// truncation splits. smem: KH, VH, VL each [256][40] = 60 KB. 2 CTA/SM.
// ---------------------------------------------------------------------------
#define AT_KH 0
#define AT_VH 20480
#define AT_VL 40960
#define AT_SMEM 61440

__global__ __launch_bounds__(256, 2) void mma_attn_kernel(
    const float* __restrict__ mb, const float* __restrict__ tb)
{
    extern __shared__ __align__(16) char smem[];
    const int tid = threadIdx.x, w = tid >> 5, lane = tid & 31;
    const int h = blockIdx.x;
    const int n = blockIdx.y;
    const uint32_t sb = smem_u32(smem);
    const size_t base = (size_t)(n * NH + h) * NN * HD;

    // stage K, Vh, Vl (row = tid, 64B each) via cp.async
    {
        const char* sK  = (const char*)(g_Kb + base) + tid * 64;
        const char* sVh = (const char*)(g_Vhb + base) + tid * 64;
        const char* sVl = (const char*)(g_Vlb + base) + tid * 64;
        uint32_t drow = (uint32_t)tid * 80;
        #pragma unroll
        for (int i = 0; i < 4; i++) {
            cp_async16(sb + AT_KH + drow + i * 16, sK + i * 16);
            cp_async16(sb + AT_VH + drow + i * 16, sVh + i * 16);
            cp_async16(sb + AT_VL + drow + i * 16, sVl + i * 16);
        }
        asm volatile("cp.async.commit_group;");
    }

    // Q fragments straight from gmem while cp.async drains
    uint32_t aQh[2][2][4];
    {
        const __nv_bfloat16* qb = g_Qb + base + (size_t)(w * 32) * HD;
        int rl = (lane >> 2), c0 = (lane & 3) * 2;
        #pragma unroll
        for (int mf = 0; mf < 2; mf++) {
            const __nv_bfloat16* qr = qb + mf * 16 * HD;
            #pragma unroll
            for (int kd = 0; kd < 2; kd++) {
                int cc = c0 + kd * 16;
                aQh[mf][kd][0] = *(const uint32_t*)(qr + rl * HD + cc);
                aQh[mf][kd][1] = *(const uint32_t*)(qr + (rl + 8) * HD + cc);
                aQh[mf][kd][2] = *(const uint32_t*)(qr + rl * HD + cc + 8);
                aQh[mf][kd][3] = *(const uint32_t*)(qr + (rl + 8) * HD + cc + 8);
            }
        }
    }
    asm volatile("cp.async.wait_group 0;" ::: "memory");
    __syncthreads();

    const int lt = lane >> 3, lr = lane & 7;
    const uint32_t bk_off = ((((lt & 2) ? 8 : 0) + lr) * 40 + ((lt & 1) ? 8 : 0)) * 2;
    const uint32_t bv_off = (uint32_t)((lt & 1) * 8 + lr) * 80 + (uint32_t)(lt >> 1) * 16;

    const int qr00 = w * 32 + (lane >> 2);
    const float* mrow = mb + (size_t)n * NN;
    const float* tr = tb + ((size_t)h * NN + qr00) * NN;   // rows +8/16/24 via imm

    float oacc[2][4][4];
    #pragma unroll
    for (int mf = 0; mf < 2; mf++)
        #pragma unroll
        for (int f = 0; f < 4; f++)
            #pragma unroll
            for (int i = 0; i < 4; i++) oacc[mf][f][i] = 0.f;
    float s00 = 0.f, s01 = 0.f, s10 = 0.f, s11 = 0.f;

    #pragma unroll 1
    for (int c = 0; c < 8; c++) {                 // 32-key chunks
        const int kc0 = c * 32;
        float sacc[2][4][4];                       // [mf][f over 4 n8][4]
        #pragma unroll
        for (int mf = 0; mf < 2; mf++)
            #pragma unroll
            for (int f = 0; f < 4; f++)
                #pragma unroll
                for (int i = 0; i < 4; i++) sacc[mf][f][i] = 0.f;

        // phase 1: S = Q K^T (wide batch: 4 independent B-LDSMs, 16 MMAs)
        #pragma unroll
        for (int kd = 0; kd < 2; kd++) {
            #pragma unroll
            for (int g = 0; g < 2; g++) {
                uint32_t bh[4];
                ldsm_x4(bh, sb + AT_KH + bk_off + (uint32_t)(kc0 + g * 16) * 80 + kd * 32);
                #pragma unroll
                for (int mf = 0; mf < 2; mf++) {
                    mma_bf16(sacc[mf][2*g],   aQh[mf][kd], bh);
                    mma_bf16(sacc[mf][2*g+1], aQh[mf][kd], bh+2);
                }
            }
        }

        // phase 2: biases + exp + sums (16 independent exps)
        #pragma unroll
        for (int f = 0; f < 4; f++) {
            int kcol = kc0 + f * 8 + 2 * (lane & 3);
            float2 mv  = *(const float2*)(mrow + kcol);
            float2 t00 = *(const float2*)(tr + kcol);
            float2 t01 = *(const float2*)(tr + kcol + 8 * NN);
            float2 t10 = *(const float2*)(tr + kcol + 16 * NN);
            float2 t11 = *(const float2*)(tr + kcol + 24 * NN);
            sacc[0][f][0] = __expf(sacc[0][f][0] + mv.x + t00.x);
            sacc[0][f][1] = __expf(sacc[0][f][1] + mv.y + t00.y);
            sacc[0][f][2] = __expf(sacc[0][f][2] + mv.x + t01.x);
            sacc[0][f][3] = __expf(sacc[0][f][3] + mv.y + t01.y);
            sacc[1][f][0] = __expf(sacc[1][f][0] + mv.x + t10.x);
            sacc[1][f][1] = __expf(sacc[1][f][1] + mv.y + t10.y);
            sacc[1][f][2] = __expf(sacc[1][f][2] + mv.x + t11.x);
            sacc[1][f][3] = __expf(sacc[1][f][3] + mv.y + t11.y);
            s00 += sacc[0][f][0] + sacc[0][f][1];
            s01 += sacc[0][f][2] + sacc[0][f][3];
            s10 += sacc[1][f][0] + sacc[1][f][1];
            s11 += sacc[1][f][2] + sacc[1][f][3];
        }

        // phase 3: O += P V (trunc splits, wide LDSM/MMA batch)
        #pragma unroll
        for (int kf = 0; kf < 2; kf++) {
            uint32_t ph[2][4], pl[2][4];
            #pragma unroll
            for (int mf = 0; mf < 2; mf++) {
                fsplit2(sacc[mf][2*kf][0],   sacc[mf][2*kf][1],   ph[mf][0], pl[mf][0]);
                fsplit2(sacc[mf][2*kf][2],   sacc[mf][2*kf][3],   ph[mf][1], pl[mf][1]);
                fsplit2(sacc[mf][2*kf+1][0], sacc[mf][2*kf+1][1], ph[mf][2], pl[mf][2]);
                fsplit2(sacc[mf][2*kf+1][2], sacc[mf][2*kf+1][3], ph[mf][3], pl[mf][3]);
            }
            uint32_t krow = (uint32_t)(kc0 + kf * 16) * 80;
            #pragma unroll
            for (int ngd = 0; ngd < 2; ngd++) {
                uint32_t bh[4], bl[4];
                uint32_t ba = sb + AT_VH + krow + bv_off + ngd * 32;
                ldsm_x4_t(bh, ba);
                ldsm_x4_t(bl, ba + (AT_VL - AT_VH));
                #pragma unroll
                for (int mf = 0; mf < 2; mf++) {
                    mma_bf16(oacc[mf][2*ngd],   ph[mf], bh);
                    mma_bf16(oacc[mf][2*ngd+1], ph[mf], bh+2);
                    mma_bf16(oacc[mf][2*ngd],   ph[mf], bl);
                    mma_bf16(oacc[mf][2*ngd+1], ph[mf], bl+2);
                    mma_bf16(oacc[mf][2*ngd],   pl[mf], bh);
                    mma_bf16(oacc[mf][2*ngd+1], pl[mf], bh+2);
                }
            }
        }
    }

    s00 += __shfl_xor_sync(0xffffffffu, s00, 1);
    s00 += __shfl_xor_sync(0xffffffffu, s00, 2);
    s01 += __shfl_xor_sync(0xffffffffu, s01, 1);
    s01 += __shfl_xor_sync(0xffffffffu, s01, 2);
    s10 += __shfl_xor_sync(0xffffffffu, s10, 1);
    s10 += __shfl_xor_sync(0xffffffffu, s10, 2);
    s11 += __shfl_xor_sync(0xffffffffu, s11, 1);
    s11 += __shfl_xor_sync(0xffffffffu, s11, 2);
    float inv[2][2] = {{1.f / s00, 1.f / s01}, {1.f / s10, 1.f / s11}};

    #pragma unroll
    for (int mf = 0; mf < 2; mf++) {
        const int rlo = n * NN + w * 32 + mf * 16 + (lane >> 2);
        const int rhi = rlo + 8;
        #pragma unroll
        for (int f = 0; f < 4; f++) {
            int d = f * 8 + 2 * (lane & 3);
            float2 glo = *(const float2*)(g_G + (size_t)rlo * NE + h * HD + d);
            float2 ghi = *(const float2*)(g_G + (size_t)rhi * NE + h * HD + d);
            uint32_t oh, ol;
            split2(oacc[mf][f][0] * inv[mf][0] * glo.x,
                   oacc[mf][f][1] * inv[mf][0] * glo.y, oh, ol);
            *(uint32_t*)(g_Ohb + (size_t)rlo * NE + h * HD + d) = oh;
            *(uint32_t*)(g_Olb + (size_t)rlo * NE + h * HD + d) = ol;
            split2(oacc[mf][f][2] * inv[mf][1] * ghi.x,
                   oacc[mf][f][3] * inv[mf][1] * ghi.y, oh, ol);
            *(uint32_t*)(g_Ohb + (size_t)rhi * NE + h * HD + d) = oh;
            *(uint32_t*)(g_Olb + (size_t)rhi * NE + h * HD + d) = ol;
        }
    }
}

// ---------------------------------------------------------------------------
// Kernel 3: output projection. X pre-split bf16 hi/lo via cp.async.
// ---------------------------------------------------------------------------
__global__ __launch_bounds__(256) void mma_out_kernel(
    const float* __restrict__ bo, float* __restrict__ out)
{
    extern __shared__ __align__(16) char smem[];
    const int tid = threadIdx.x, w = tid >> 5, lane = tid & 31;
    const int mi = w & 1, nh = w >> 1;
    const int r0 = blockIdx.x * 64;
    const uint32_t sb = smem_u32(smem);

    {
        const char* srcH = (const char*)g_Wh[4];
        const char* srcL = (const char*)g_Wl[4];
        for (int i = tid; i < 2176; i += 256) {
            cp_async16(sb + GX_WH + i * 16, srcH + i * 16);
            cp_async16(sb + GX_WL + i * 16, srcL + i * 16);
        }
        int r = tid >> 2, c0 = (tid & 3) * 32;
        const char* sXh = (const char*)(g_Ohb + (size_t)(r0 + r) * NE + c0);
        const char* sXl = (const char*)(g_Olb + (size_t)(r0 + r) * NE + c0);
        uint32_t drow = (uint32_t)r * 272 + (uint32_t)c0 * 2;
        #pragma unroll
        for (int i = 0; i < 4; i++) {
            cp_async16(sb + GX_XH + drow + i * 16, sXh + i * 16);
            cp_async16(sb + GX_XL + drow + i * 16, sXl + i * 16);
        }
        asm volatile("cp.async.commit_group;");
    }
    asm volatile("cp.async.wait_group 0;" ::: "memory");
    __syncthreads();

    const int lt = lane >> 3, lr = lane & 7;
    const uint32_t a_off = ((uint32_t)(mi * 32 + ((lt & 1) ? 8 : 0) + lr) * 136
                           + ((lt & 2) ? 8 : 0)) * 2;
    const uint32_t b_off = ((uint32_t)(nh * 32 + ((lt & 2) ? 8 : 0) + lr) * 136
                           + ((lt & 1) ? 8 : 0)) * 2;

    float acc[2][2][2][4];
    #pragma unroll
    for (int mf = 0; mf < 2; mf++)
        #pragma unroll
        for (int g = 0; g < 2; g++)
            #pragma unroll
            for (int j = 0; j < 2; j++)
                #pragma unroll
                for (int i = 0; i < 4; i++) acc[mf][g][j][i] = 0.f;

    #pragma unroll
    for (int k = 0; k < 8; k++) {
        uint32_t ah[2][4], al[2][4];
        #pragma unroll
        for (int mf = 0; mf < 2; mf++) {
            ldsm_x4(ah[mf], sb + GX_XH + a_off + mf * 4352 + k * 32);
            ldsm_x4(al[mf], sb + GX_XL + a_off + mf * 4352 + k * 32);
        }
        #pragma unroll
        for (int g = 0; g < 2; g++) {
            uint32_t bh[4], bl[4];
            uint32_t ba = sb + GX_WH + b_off + g * 4352 + k * 32;
            ldsm_x4(bh, ba);
            ldsm_x4(bl, ba + (GX_WL - GX_WH));
            #pragma unroll
            for (int mf = 0; mf < 2; mf++) {
                mma_bf16(acc[mf][g][0], ah[mf], bh); mma_bf16(acc[mf][g][1], ah[mf], bh+2);
                mma_bf16(acc[mf][g][0], ah[mf], bl); mma_bf16(acc[mf][g][1], ah[mf], bl+2);
                mma_bf16(acc[mf][g][0], al[mf], bh); mma_bf16(acc[mf][g][1], al[mf], bh+2);
            }
        }
    }

    #pragma unroll
    for (int mf = 0; mf < 2; mf++) {
        const int rlo = r0 + mi * 32 + mf * 16 + (lane >> 2);
        const int rhi = rlo + 8;
        #pragma unroll
        for (int g = 0; g < 2; g++)
            #pragma unroll
            for (int j = 0; j < 2; j++) {
                int cc = nh * 32 + g * 16 + j * 8 + 2 * (lane & 3);
                float b0 = bo[cc], b1 = bo[cc + 1];
                float* a = acc[mf][g][j];
                *(float2*)(out + (size_t)rlo * CIN + cc) = make_float2(a[0] + b0, a[1] + b1);
                *(float2*)(out + (size_t)rhi * CIN + cc) = make_float2(a[2] + b0, a[3] + b1);
            }
    }
}

// ---------------------------------------------------------------------------
extern "C" void kernel_launch(void* const* d_in, const int* in_sizes, int n_in,
                              void* d_out, int out_size)
{
    const float* qx  = (const float*)d_in[0];
    const float* kvx = (const float*)d_in[1];
    const float* mb  = (const float*)d_in[2];
    const float* tb  = (const float*)d_in[3];
    const float* wq  = (const float*)d_in[4];
    const float* wk  = (const float*)d_in[5];
    const float* wv  = (const float*)d_in[6];
    const float* wg  = (const float*)d_in[7];
    const float* bg  = (const float*)d_in[8];
    const float* wo  = (const float*)d_in[9];
    const float* bo  = (const float*)d_in[10];
    float* out = (float*)d_out;

    cudaFuncSetAttribute(proj_light_kernel, cudaFuncAttributeMaxDynamicSharedMemorySize, PL_SMEM);
    cudaFuncSetAttribute(proj_heavy_kernel, cudaFuncAttributeMaxDynamicSharedMemorySize, GX_SMEM);
    cudaFuncSetAttribute(mma_attn_kernel,   cudaFuncAttributeMaxDynamicSharedMemorySize, AT_SMEM);
    cudaFuncSetAttribute(mma_out_kernel,    cudaFuncAttributeMaxDynamicSharedMemorySize, GX_SMEM);

    convw_kernel<<<5, 256>>>(wq, wk, wv, wg, wo);
    proj_light_kernel<<<dim3(1024, 2), 256, PL_SMEM>>>(qx, kvx);
    proj_heavy_kernel<<<dim3(1024, 2), 256, GX_SMEM>>>(qx, kvx, bg);
    mma_attn_kernel<<<dim3(NH, NN), 256, AT_SMEM>>>(mb, tb);
    mma_out_kernel<<<1024, 256, GX_SMEM>>>(bo, out);
}